// round 13
// baseline (speedup 1.0000x reference)
#include <cuda_runtime.h>
#include <math.h>

#define B 8
#define N 2048
#define FIN 128
#define FOUT 64
#define ALPHA 0.2f
#define NEG_BIG (-9000000000000000.0f)

#define TI 64
#define TJ 64

// Scratch (allocation-free rule: device globals)
__device__ float g_wh[B * N * FOUT];   // 4 MB
__device__ float g_s1[B * N];
__device__ float g_s2[B * N];
__device__ float g_c[B * N];           // c_i = rowmax + log(rowsum)

// ---------------------------------------------------------------------------
// K1: wh = x @ W ; s1 = wh @ a1 ; s2 = wh @ a2.   One warp per row.
// ---------------------------------------------------------------------------
__global__ __launch_bounds__(256) void k1_proj(const float* __restrict__ x,
                                               const float* __restrict__ W,
                                               const float* __restrict__ w2) {
    __shared__ float xs[8][FIN];
    int warp = threadIdx.x >> 5, lane = threadIdx.x & 31;
    int row = blockIdx.x * 8 + warp;            // [0, B*N)
    const float* xr = x + (size_t)row * FIN;
    xs[warp][lane]      = xr[lane];
    xs[warp][lane + 32] = xr[lane + 32];
    xs[warp][lane + 64] = xr[lane + 64];
    xs[warp][lane + 96] = xr[lane + 96];
    __syncwarp();

    float wh0 = 0.f, wh1 = 0.f;
#pragma unroll 8
    for (int k = 0; k < FIN; ++k) {
        float xv = xs[warp][k];
        wh0 = fmaf(xv, W[k * FOUT + lane],      wh0);
        wh1 = fmaf(xv, W[k * FOUT + lane + 32], wh1);
    }
    g_wh[(size_t)row * FOUT + lane]      = wh0;
    g_wh[(size_t)row * FOUT + lane + 32] = wh1;

    float p1 = wh0 * w2[lane]      + wh1 * w2[lane + 32];
    float p2 = wh0 * w2[64 + lane] + wh1 * w2[96 + lane];
#pragma unroll
    for (int off = 16; off > 0; off >>= 1) {
        p1 += __shfl_xor_sync(0xffffffffu, p1, off);
        p2 += __shfl_xor_sync(0xffffffffu, p2, off);
    }
    if (lane == 0) { g_s1[row] = p1; g_s2[row] = p2; }
}

// ---------------------------------------------------------------------------
// K2: per-row online softmax stats over masked leaky scores.
//     Stores c_i = m_i + log(l_i) so attention = exp(e - c_i) directly.
// ---------------------------------------------------------------------------
__global__ __launch_bounds__(256) void k2_rowstats(const int* __restrict__ adj) {
    int warp = threadIdx.x >> 5, lane = threadIdx.x & 31;
    int row = blockIdx.x * 8 + warp;            // [0, B*N)
    int b = row >> 11;                          // / N
    int i = row & (N - 1);
    const int* arow = adj + ((size_t)b * N + i) * N;
    const float* s2b = g_s2 + b * N;
    float s1v = g_s1[row];

    float m = -3.0e38f, l = 0.f;
    for (int j = lane; j < N; j += 32) {
        int a = arow[j];
        float t = s1v + s2b[j];
        float lk = t > 0.f ? t : ALPHA * t;
        float e = (a > 0) ? lk : NEG_BIG;
        if (e > m) { l = l * __expf(m - e) + 1.f; m = e; }
        else       { l += __expf(e - m); }
    }
    // warp combine (m, l)
#pragma unroll
    for (int off = 16; off > 0; off >>= 1) {
        float mo = __shfl_xor_sync(0xffffffffu, m, off);
        float lo = __shfl_xor_sync(0xffffffffu, l, off);
        float mm = fmaxf(m, mo);
        l = l * __expf(m - mm) + lo * __expf(mo - mm);
        m = mm;
    }
    if (lane == 0) g_c[row] = m + __logf(l);
}

// ---------------------------------------------------------------------------
// K3: out = elu( P @ WH ), P generated on the fly per tile.
//     Block: 64 i-rows, 256 threads; thread = 2 rows x 8 outputs.
//     Accumulate with packed fma.rn.f32x2 (2x fp32 FMA throughput).
// ---------------------------------------------------------------------------
__global__ __launch_bounds__(256) void k3_attn(const int* __restrict__ adj,
                                               float* __restrict__ out) {
    __shared__ float wh_s[TJ][FOUT];        // 16 KB
    __shared__ float p_s[TI][TJ + 1];       // padded: conflict-free row-strided reads
    __shared__ float s2_s[TJ];
    __shared__ float s1_s[TI];
    __shared__ float c_s[TI];

    int t = threadIdx.x;
    int b = blockIdx.y;
    int i0 = blockIdx.x * TI;
    const float* whb = g_wh + (size_t)b * N * FOUT;
    const int* adjb = adj + (size_t)b * N * N;

    if (t < TI) {
        s1_s[t] = g_s1[b * N + i0 + t];
        c_s[t]  = g_c[b * N + i0 + t];
    }

    int cg = t & 7;        // output group: o = cg*8
    int rg = t >> 3;       // 0..31 -> rows rg*2, rg*2+1
    int o = cg * 8;

    unsigned long long acc[2][4];
#pragma unroll
    for (int r = 0; r < 2; ++r)
#pragma unroll
        for (int q = 0; q < 4; ++q) acc[r][q] = 0ull;

    int jq = t & 63;       // j for score phase (coalesced adj)
    int iq = t >> 6;       // 0..3

    for (int jt = 0; jt < N / TJ; ++jt) {
        int j0 = jt * TJ;

        __syncthreads();   // protect wh_s/p_s from previous accumulate phase
        // load WH tile (16 threads x float4 per row, fully coalesced) + s2
#pragma unroll
        for (int q = 0; q < 4; ++q) {
            int lin = t + q * 256;          // 0..1023
            int row = lin >> 4;
            int c4 = (lin & 15) * 4;
            *(float4*)&wh_s[row][c4] =
                *(const float4*)&whb[(size_t)(j0 + row) * FOUT + c4];
        }
        if (t < TJ) s2_s[t] = g_s2[b * N + j0 + t];
        __syncthreads();

        // score phase: p = exp(masked_leaky(s1_i + s2_j) - c_i), one exp per elem
#pragma unroll 4
        for (int q = 0; q < 16; ++q) {
            int i = iq * 16 + q;
            int a = adjb[(size_t)(i0 + i) * N + j0 + jq];
            float tt = s1_s[i] + s2_s[jq];
            float lk = tt > 0.f ? tt : ALPHA * tt;
            float e = (a > 0) ? lk : NEG_BIG;      // keeps all-masked rows exact
            p_s[i][jq] = __expf(e - c_s[i]);
        }
        __syncthreads();

        // accumulate phase: packed f32x2 FMAs, 16 FMA per j per thread
#pragma unroll 4
        for (int j = 0; j < TJ; ++j) {
            ulonglong2 wa = *(const ulonglong2*)&wh_s[j][o];
            ulonglong2 wb = *(const ulonglong2*)&wh_s[j][o + 4];
#pragma unroll
            for (int r = 0; r < 2; ++r) {
                float p = p_s[rg * 2 + r][j];
                unsigned long long pp;
                asm("mov.b64 %0, {%1, %1};" : "=l"(pp) : "r"(__float_as_uint(p)));
                asm("fma.rn.f32x2 %0, %1, %2, %0;" : "+l"(acc[r][0]) : "l"(wa.x), "l"(pp));
                asm("fma.rn.f32x2 %0, %1, %2, %0;" : "+l"(acc[r][1]) : "l"(wa.y), "l"(pp));
                asm("fma.rn.f32x2 %0, %1, %2, %0;" : "+l"(acc[r][2]) : "l"(wb.x), "l"(pp));
                asm("fma.rn.f32x2 %0, %1, %2, %0;" : "+l"(acc[r][3]) : "l"(wb.y), "l"(pp));
            }
        }
    }

    // epilogue: ELU + store
#pragma unroll
    for (int r = 0; r < 2; ++r) {
        int i = i0 + rg * 2 + r;
        float vals[8];
#pragma unroll
        for (int q = 0; q < 4; ++q) {
            vals[q * 2]     = __uint_as_float((unsigned)(acc[r][q] & 0xffffffffu));
            vals[q * 2 + 1] = __uint_as_float((unsigned)(acc[r][q] >> 32));
        }
#pragma unroll
        for (int q = 0; q < 8; ++q) {
            float v = vals[q];
            vals[q] = v > 0.f ? v : (expf(v) - 1.f);
        }
        float4* dst = (float4*)&out[((size_t)b * N + i) * FOUT + o];
        dst[0] = make_float4(vals[0], vals[1], vals[2], vals[3]);
        dst[1] = make_float4(vals[4], vals[5], vals[6], vals[7]);
    }
}

// ---------------------------------------------------------------------------
extern "C" void kernel_launch(void* const* d_in, const int* in_sizes, int n_in,
                              void* d_out, int out_size) {
    const float* x   = (const float*)d_in[0];
    const int*   adj = (const int*)d_in[1];
    const float* W   = (const float*)d_in[2];
    const float* w2  = (const float*)d_in[3];
    float* out = (float*)d_out;

    k1_proj<<<(B * N) / 8, 256>>>(x, W, w2);
    k2_rowstats<<<(B * N) / 8, 256>>>(adj);
    dim3 g3(N / TI, B);
    k3_attn<<<g3, 256>>>(adj, out);
}

// round 14
// speedup vs baseline: 1.0043x; 1.0043x over previous
#include <cuda_runtime.h>
#include <math.h>

#define B 8
#define N 2048
#define FIN 128
#define FOUT 64
#define ALPHA 0.2f
#define NEG_BIG (-9000000000000000.0f)

#define TI 64
#define TJ 64

// Scratch (allocation-free rule: device globals)
__device__ float g_wh[B * N * FOUT];   // 4 MB
__device__ float g_s1[B * N];
__device__ float g_s2[B * N];
__device__ float g_c[B * N];           // c_i = rowmax + log(rowsum)

// ---------------------------------------------------------------------------
// K1: wh = x @ W ; s1 = wh @ a1 ; s2 = wh @ a2.   One warp per row.
// ---------------------------------------------------------------------------
__global__ __launch_bounds__(256) void k1_proj(const float* __restrict__ x,
                                               const float* __restrict__ W,
                                               const float* __restrict__ w2) {
    __shared__ float xs[8][FIN];
    int warp = threadIdx.x >> 5, lane = threadIdx.x & 31;
    int row = blockIdx.x * 8 + warp;            // [0, B*N)
    const float* xr = x + (size_t)row * FIN;
    xs[warp][lane]      = xr[lane];
    xs[warp][lane + 32] = xr[lane + 32];
    xs[warp][lane + 64] = xr[lane + 64];
    xs[warp][lane + 96] = xr[lane + 96];
    __syncwarp();

    float wh0 = 0.f, wh1 = 0.f;
#pragma unroll 8
    for (int k = 0; k < FIN; ++k) {
        float xv = xs[warp][k];
        wh0 = fmaf(xv, W[k * FOUT + lane],      wh0);
        wh1 = fmaf(xv, W[k * FOUT + lane + 32], wh1);
    }
    g_wh[(size_t)row * FOUT + lane]      = wh0;
    g_wh[(size_t)row * FOUT + lane + 32] = wh1;

    float p1 = wh0 * w2[lane]      + wh1 * w2[lane + 32];
    float p2 = wh0 * w2[64 + lane] + wh1 * w2[96 + lane];
#pragma unroll
    for (int off = 16; off > 0; off >>= 1) {
        p1 += __shfl_xor_sync(0xffffffffu, p1, off);
        p2 += __shfl_xor_sync(0xffffffffu, p2, off);
    }
    if (lane == 0) { g_s1[row] = p1; g_s2[row] = p2; }
}

// ---------------------------------------------------------------------------
// K2: per-row online softmax stats over masked leaky scores.
//     Stores c_i = m_i + log(l_i) so attention = exp(e - c_i) directly.
// ---------------------------------------------------------------------------
__global__ __launch_bounds__(256) void k2_rowstats(const int* __restrict__ adj) {
    int warp = threadIdx.x >> 5, lane = threadIdx.x & 31;
    int row = blockIdx.x * 8 + warp;            // [0, B*N)
    int b = row >> 11;                          // / N
    int i = row & (N - 1);
    const int* arow = adj + ((size_t)b * N + i) * N;
    const float* s2b = g_s2 + b * N;
    float s1v = g_s1[row];

    float m = -3.0e38f, l = 0.f;
    for (int j = lane; j < N; j += 32) {
        int a = arow[j];
        float t = s1v + s2b[j];
        float lk = t > 0.f ? t : ALPHA * t;
        float e = (a > 0) ? lk : NEG_BIG;
        if (e > m) { l = l * __expf(m - e) + 1.f; m = e; }
        else       { l += __expf(e - m); }
    }
    // warp combine (m, l)
#pragma unroll
    for (int off = 16; off > 0; off >>= 1) {
        float mo = __shfl_xor_sync(0xffffffffu, m, off);
        float lo = __shfl_xor_sync(0xffffffffu, l, off);
        float mm = fmaxf(m, mo);
        l = l * __expf(m - mm) + lo * __expf(mo - mm);
        m = mm;
    }
    if (lane == 0) g_c[row] = m + __logf(l);
}

// ---------------------------------------------------------------------------
// K3: out = elu( P @ WH ), P generated on the fly per tile.
//     Block: 64 i-rows, 256 threads; thread = 2 rows x 8 outputs.
//     Accumulate with packed fma.rn.f32x2 (2x fp32 FMA throughput).
// ---------------------------------------------------------------------------
__global__ __launch_bounds__(256) void k3_attn(const int* __restrict__ adj,
                                               float* __restrict__ out) {
    __shared__ float wh_s[TJ][FOUT];        // 16 KB
    __shared__ float p_s[TI][TJ + 1];       // padded: conflict-free row-strided reads
    __shared__ float s2_s[TJ];
    __shared__ float s1_s[TI];
    __shared__ float c_s[TI];

    int t = threadIdx.x;
    int b = blockIdx.y;
    int i0 = blockIdx.x * TI;
    const float* whb = g_wh + (size_t)b * N * FOUT;
    const int* adjb = adj + (size_t)b * N * N;

    if (t < TI) {
        s1_s[t] = g_s1[b * N + i0 + t];
        c_s[t]  = g_c[b * N + i0 + t];
    }

    int cg = t & 7;        // output group: o = cg*8
    int rg = t >> 3;       // 0..31 -> rows rg*2, rg*2+1
    int o = cg * 8;

    unsigned long long acc[2][4];
#pragma unroll
    for (int r = 0; r < 2; ++r)
#pragma unroll
        for (int q = 0; q < 4; ++q) acc[r][q] = 0ull;

    int jq = t & 63;       // j for score phase (coalesced adj)
    int iq = t >> 6;       // 0..3

    for (int jt = 0; jt < N / TJ; ++jt) {
        int j0 = jt * TJ;

        __syncthreads();   // protect wh_s/p_s from previous accumulate phase
        // load WH tile (16 threads x float4 per row, fully coalesced) + s2
#pragma unroll
        for (int q = 0; q < 4; ++q) {
            int lin = t + q * 256;          // 0..1023
            int row = lin >> 4;
            int c4 = (lin & 15) * 4;
            *(float4*)&wh_s[row][c4] =
                *(const float4*)&whb[(size_t)(j0 + row) * FOUT + c4];
        }
        if (t < TJ) s2_s[t] = g_s2[b * N + j0 + t];
        __syncthreads();

        // score phase: p = exp(masked_leaky(s1_i + s2_j) - c_i), one exp per elem
#pragma unroll 4
        for (int q = 0; q < 16; ++q) {
            int i = iq * 16 + q;
            int a = adjb[(size_t)(i0 + i) * N + j0 + jq];
            float tt = s1_s[i] + s2_s[jq];
            float lk = tt > 0.f ? tt : ALPHA * tt;
            float e = (a > 0) ? lk : NEG_BIG;      // keeps all-masked rows exact
            p_s[i][jq] = __expf(e - c_s[i]);
        }
        __syncthreads();

        // accumulate phase: packed f32x2 FMAs, 16 FMA per j per thread
#pragma unroll 4
        for (int j = 0; j < TJ; ++j) {
            ulonglong2 wa = *(const ulonglong2*)&wh_s[j][o];
            ulonglong2 wb = *(const ulonglong2*)&wh_s[j][o + 4];
#pragma unroll
            for (int r = 0; r < 2; ++r) {
                float p = p_s[rg * 2 + r][j];
                unsigned long long pp;
                asm("mov.b64 %0, {%1, %1};" : "=l"(pp) : "r"(__float_as_uint(p)));
                asm("fma.rn.f32x2 %0, %1, %2, %0;" : "+l"(acc[r][0]) : "l"(wa.x), "l"(pp));
                asm("fma.rn.f32x2 %0, %1, %2, %0;" : "+l"(acc[r][1]) : "l"(wa.y), "l"(pp));
                asm("fma.rn.f32x2 %0, %1, %2, %0;" : "+l"(acc[r][2]) : "l"(wb.x), "l"(pp));
                asm("fma.rn.f32x2 %0, %1, %2, %0;" : "+l"(acc[r][3]) : "l"(wb.y), "l"(pp));
            }
        }
    }

    // epilogue: ELU + store
#pragma unroll
    for (int r = 0; r < 2; ++r) {
        int i = i0 + rg * 2 + r;
        float vals[8];
#pragma unroll
        for (int q = 0; q < 4; ++q) {
            vals[q * 2]     = __uint_as_float((unsigned)(acc[r][q] & 0xffffffffu));
            vals[q * 2 + 1] = __uint_as_float((unsigned)(acc[r][q] >> 32));
        }
#pragma unroll
        for (int q = 0; q < 8; ++q) {
            float v = vals[q];
            vals[q] = v > 0.f ? v : (expf(v) - 1.f);
        }
        float4* dst = (float4*)&out[((size_t)b * N + i) * FOUT + o];
        dst[0] = make_float4(vals[0], vals[1], vals[2], vals[3]);
        dst[1] = make_float4(vals[4], vals[5], vals[6], vals[7]);
    }
}

// ---------------------------------------------------------------------------
extern "C" void kernel_launch(void* const* d_in, const int* in_sizes, int n_in,
                              void* d_out, int out_size) {
    const float* x   = (const float*)d_in[0];
    const int*   adj = (const int*)d_in[1];
    const float* W   = (const float*)d_in[2];
    const float* w2  = (const float*)d_in[3];
    float* out = (float*)d_out;

    k1_proj<<<(B * N) / 8, 256>>>(x, W, w2);
    k2_rowstats<<<(B * N) / 8, 256>>>(adj);
    dim3 g3(N / TI, B);
    k3_attn<<<g3, 256>>>(adj, out);
}

// round 15
// speedup vs baseline: 2.2633x; 2.2536x over previous
#include <cuda_runtime.h>
#include <math.h>

#define B 8
#define N 2048
#define FIN 128
#define FOUT 64
#define ALPHA 0.2f

#define TI 64
#define TJ 64
#define SPLIT 2
#define JTILES ((N / SPLIT) / TJ)   // 16

typedef unsigned long long u64;

// Scratch (allocation-free rule: device globals)
__device__ float g_wh[B * N * FOUT];                 // 4 MB
__device__ float g_s1[B * N];
__device__ float g_s2[B * N];
__device__ float g_acc[SPLIT * B * N * FOUT];        // 8 MB partials
__device__ float g_l[SPLIT * B * N];                 // partial row sums

__device__ __forceinline__ u64 bcast2(float v) {
    u64 r;
    asm("mov.b64 %0, {%1, %1};" : "=l"(r) : "r"(__float_as_uint(v)));
    return r;
}
__device__ __forceinline__ u64 pack2(float a, float b) {
    u64 r;
    asm("mov.b64 %0, {%1, %2};" : "=l"(r) : "r"(__float_as_uint(a)), "r"(__float_as_uint(b)));
    return r;
}
__device__ __forceinline__ void fma2(u64& acc, u64 a, u64 b) {
    asm("fma.rn.f32x2 %0, %1, %2, %0;" : "+l"(acc) : "l"(a), "l"(b));
}
__device__ __forceinline__ void add2(u64& acc, u64 a) {
    asm("add.rn.f32x2 %0, %1, %0;" : "+l"(acc) : "l"(a));
}
__device__ __forceinline__ float lo2(u64 v) { return __uint_as_float((unsigned)(v & 0xffffffffu)); }
__device__ __forceinline__ float hi2(u64 v) { return __uint_as_float((unsigned)(v >> 32)); }

// ---------------------------------------------------------------------------
// K1: wh = x @ W ; s1 = wh @ a1 ; s2 = wh @ a2.
// Block: 256 threads, 32 rows. W staged in smem (32 KB), x via broadcast LDG.
// Thread (r = t>>3, cg = t&7) owns cols [cg*4, cg*4+4) and [32+cg*4, ...+4).
// ---------------------------------------------------------------------------
__global__ __launch_bounds__(256) void k1_proj(const float* __restrict__ x,
                                               const float* __restrict__ W,
                                               const float* __restrict__ w2) {
    __shared__ __align__(16) float Ws[FIN][FOUT];    // 32 KB
    int t = threadIdx.x;

#pragma unroll
    for (int q = 0; q < 8; ++q) {
        int lin = t + q * 256;                       // 2048 float4s
        ((float4*)Ws)[lin] = ((const float4*)W)[lin];
    }
    __syncthreads();

    int r = t >> 3, cg = t & 7;
    int row = blockIdx.x * 32 + r;
    int c1 = cg * 4, c2 = 32 + cg * 4;
    const float4* xr = (const float4*)(x + (size_t)row * FIN);

    u64 acc[4] = {0ull, 0ull, 0ull, 0ull};
#pragma unroll 8
    for (int kc = 0; kc < FIN / 4; ++kc) {
        float4 xq = __ldg(&xr[kc]);
        float xv[4] = {xq.x, xq.y, xq.z, xq.w};
#pragma unroll
        for (int q = 0; q < 4; ++q) {
            int k = kc * 4 + q;
            u64 xx = bcast2(xv[q]);
            ulonglong2 wa = *(const ulonglong2*)&Ws[k][c1];
            ulonglong2 wb = *(const ulonglong2*)&Ws[k][c2];
            fma2(acc[0], wa.x, xx); fma2(acc[1], wa.y, xx);
            fma2(acc[2], wb.x, xx); fma2(acc[3], wb.y, xx);
        }
    }

    float wv[8];
    wv[0] = lo2(acc[0]); wv[1] = hi2(acc[0]); wv[2] = lo2(acc[1]); wv[3] = hi2(acc[1]);
    wv[4] = lo2(acc[2]); wv[5] = hi2(acc[2]); wv[6] = lo2(acc[3]); wv[7] = hi2(acc[3]);

    *(float4*)&g_wh[(size_t)row * FOUT + c1] = make_float4(wv[0], wv[1], wv[2], wv[3]);
    *(float4*)&g_wh[(size_t)row * FOUT + c2] = make_float4(wv[4], wv[5], wv[6], wv[7]);

    float4 a1a = *(const float4*)&w2[c1];
    float4 a1b = *(const float4*)&w2[c2];
    float4 a2a = *(const float4*)&w2[FOUT + c1];
    float4 a2b = *(const float4*)&w2[FOUT + c2];
    float p1 = wv[0]*a1a.x + wv[1]*a1a.y + wv[2]*a1a.z + wv[3]*a1a.w
             + wv[4]*a1b.x + wv[5]*a1b.y + wv[6]*a1b.z + wv[7]*a1b.w;
    float p2 = wv[0]*a2a.x + wv[1]*a2a.y + wv[2]*a2a.z + wv[3]*a2a.w
             + wv[4]*a2b.x + wv[5]*a2b.y + wv[6]*a2b.z + wv[7]*a2b.w;
#pragma unroll
    for (int off = 4; off > 0; off >>= 1) {
        p1 += __shfl_xor_sync(0xffffffffu, p1, off);
        p2 += __shfl_xor_sync(0xffffffffu, p2, off);
    }
    if (cg == 0) { g_s1[row] = p1; g_s2[row] = p2; }
}

// ---------------------------------------------------------------------------
// K2: fused flash-GAT. Unnormalized p = mask * exp(leakyrelu(s1_i + s2_j))
// (bounded, no max-subtraction needed). Accumulates acc = sum p*wh and
// l = sum p in one adj pass. Grid split over j (SPLIT partials).
// Block: 64 i-rows, 256 threads; thread = 2 rows x (4+4 cols).
// ---------------------------------------------------------------------------
__global__ __launch_bounds__(256) void k2_attn(const int* __restrict__ adj) {
    __shared__ __align__(16) float wh_s[TJ][68];     // 16B-aligned rows, 1-wf reads
    __shared__ __align__(16) float p_s[TJ][66];      // [j][i], float2 reads
    __shared__ float s1_s[TI];
    __shared__ float s2_s[TJ];

    int t = threadIdx.x;
    int b = blockIdx.y;
    int i0 = blockIdx.x * TI;
    int z = blockIdx.z;
    int jbase = z * (N / SPLIT);

    const int* adjb = adj + (size_t)b * N * N;
    const float* whb = g_wh + (size_t)b * N * FOUT;

    int cg = t & 7, rg = t >> 3;
    int c1 = cg * 4, c2 = 32 + cg * 4;
    int iq = t >> 6, jq = t & 63;

    if (t < TI) s1_s[t] = g_s1[b * N + i0 + t];

    u64 acc[2][4];
#pragma unroll
    for (int r = 0; r < 2; ++r)
#pragma unroll
        for (int q = 0; q < 4; ++q) acc[r][q] = 0ull;
    u64 lacc = 0ull;

    // adj software prefetch: 16 rows for this thread's (iq, jq) column
    const int* aptr = adjb + (size_t)(i0 + iq * 16) * N + jbase + jq;
    int areg[16];
#pragma unroll
    for (int q = 0; q < 16; ++q) areg[q] = aptr[(size_t)q * N];

    for (int jt = 0; jt < JTILES; ++jt) {
        int j0 = jbase + jt * TJ;

        __syncthreads();   // prev accumulate done; also covers s1_s on iter 0
#pragma unroll
        for (int q = 0; q < 4; ++q) {
            int lin = t + q * 256;
            int row = lin >> 4;
            int c4 = (lin & 15) * 4;
            *(float4*)&wh_s[row][c4] =
                *(const float4*)&whb[(size_t)(j0 + row) * FOUT + c4];
        }
        if (t < TJ) s2_s[t] = g_s2[b * N + j0 + t];
        __syncthreads();

        // score phase -> transposed p_s[j][i]
        float s2v = s2_s[jq];
#pragma unroll
        for (int q = 0; q < 16; ++q) {
            int i = iq * 16 + q;
            float tt = s1_s[i] + s2v;
            float lk = tt > 0.f ? tt : ALPHA * tt;
            p_s[jq][i] = (areg[q] > 0) ? __expf(lk) : 0.f;
        }

        // prefetch next tile's adj while others finish scores / we sync
        if (jt + 1 < JTILES) {
            const int* ap = aptr + (jt + 1) * TJ;
#pragma unroll
            for (int q = 0; q < 16; ++q) areg[q] = ap[(size_t)q * N];
        }
        __syncthreads();

        // accumulate: 3 smem wavefronts + 9 fma-pipe issues per j per warp
#pragma unroll 8
        for (int j = 0; j < TJ; ++j) {
            float2 p2 = *(const float2*)&p_s[j][rg * 2];
            ulonglong2 wa = *(const ulonglong2*)&wh_s[j][c1];
            ulonglong2 wb = *(const ulonglong2*)&wh_s[j][c2];
            u64 pp0 = bcast2(p2.x);
            u64 pp1 = bcast2(p2.y);
            fma2(acc[0][0], wa.x, pp0); fma2(acc[0][1], wa.y, pp0);
            fma2(acc[0][2], wb.x, pp0); fma2(acc[0][3], wb.y, pp0);
            fma2(acc[1][0], wa.x, pp1); fma2(acc[1][1], wa.y, pp1);
            fma2(acc[1][2], wb.x, pp1); fma2(acc[1][3], wb.y, pp1);
            add2(lacc, pack2(p2.x, p2.y));
        }
    }

    // epilogue: write partials
    size_t pbase = ((size_t)z * (B * N) + (size_t)b * N) * FOUT;
#pragma unroll
    for (int r = 0; r < 2; ++r) {
        int i = i0 + rg * 2 + r;
        *(float4*)&g_acc[pbase + (size_t)i * FOUT + c1] =
            make_float4(lo2(acc[r][0]), hi2(acc[r][0]), lo2(acc[r][1]), hi2(acc[r][1]));
        *(float4*)&g_acc[pbase + (size_t)i * FOUT + c2] =
            make_float4(lo2(acc[r][2]), hi2(acc[r][2]), lo2(acc[r][3]), hi2(acc[r][3]));
    }
    if (cg == 0) {
        int i = i0 + rg * 2;
        g_l[(size_t)z * (B * N) + b * N + i]     = lo2(lacc);
        g_l[(size_t)z * (B * N) + b * N + i + 1] = hi2(lacc);
    }
}

// ---------------------------------------------------------------------------
// K3: combine split partials, normalize, ELU.
// ---------------------------------------------------------------------------
#define TOT4 (B * N * FOUT / 4)   // 262144 float4s per split
__global__ __launch_bounds__(256) void k3_fin(float* __restrict__ out) {
    int g = blockIdx.x * 256 + threadIdx.x;   // float4 index
    int row = g >> 4;
    float l = g_l[row] + g_l[B * N + row];
    float inv = (l > 0.f) ? (1.f / l) : 0.f;
    float4 a = ((const float4*)g_acc)[g];
    float4 c = ((const float4*)g_acc)[TOT4 + g];
    float v[4] = {(a.x + c.x) * inv, (a.y + c.y) * inv,
                  (a.z + c.z) * inv, (a.w + c.w) * inv};
#pragma unroll
    for (int q = 0; q < 4; ++q) v[q] = v[q] > 0.f ? v[q] : expm1f(v[q]);
    ((float4*)out)[g] = make_float4(v[0], v[1], v[2], v[3]);
}

// ---------------------------------------------------------------------------
extern "C" void kernel_launch(void* const* d_in, const int* in_sizes, int n_in,
                              void* d_out, int out_size) {
    const float* x   = (const float*)d_in[0];
    const int*   adj = (const int*)d_in[1];
    const float* W   = (const float*)d_in[2];
    const float* w2  = (const float*)d_in[3];
    float* out = (float*)d_out;

    k1_proj<<<(B * N) / 32, 256>>>(x, W, w2);
    dim3 g2(N / TI, B, SPLIT);
    k2_attn<<<g2, 256>>>(adj);
    k3_fin<<<TOT4 / 256, 256>>>(out);
}